// round 4
// baseline (speedup 1.0000x reference)
#include <cuda_runtime.h>
#include <stdint.h>
#include <stdio.h>

// Problem constants (fixed shapes for this bench)
#define VV       128000
#define VV4      (VV / 4)
#define NTHREADS 1024
#define CAP      2048   // candidate buffer capacity per row

// ---------------------------------------------------------------------------
// JAX threefry2x32. key = jax.random.key(42) -> (k1, k2) = (0, 42).
// Generic block: given (x0_init, x1_init), run 20 rounds, return both lanes.
// ---------------------------------------------------------------------------
__device__ __forceinline__ uint32_t rotl32(uint32_t x, int r) {
    return (x << r) | (x >> (32 - r));
}

__device__ __forceinline__ void tf2x32(uint32_t c0, uint32_t c1,
                                       uint32_t& o0, uint32_t& o1) {
    const uint32_t ks0 = 0u;
    const uint32_t ks1 = 42u;
    const uint32_t ks2 = 0x1BD11BDAu ^ 0u ^ 42u;   // 0x1BD11BF0
    uint32_t x0 = c0 + ks0;
    uint32_t x1 = c1 + ks1;
#define TF_RND(r) { x0 += x1; x1 = rotl32(x1, (r)); x1 ^= x0; }
    TF_RND(13) TF_RND(15) TF_RND(26) TF_RND(6)   x0 += ks1; x1 += ks2 + 1u;
    TF_RND(17) TF_RND(29) TF_RND(16) TF_RND(24)  x0 += ks2; x1 += ks0 + 2u;
    TF_RND(13) TF_RND(15) TF_RND(26) TF_RND(6)   x0 += ks0; x1 += ks1 + 3u;
    TF_RND(17) TF_RND(29) TF_RND(16) TF_RND(24)  x0 += ks1; x1 += ks2 + 4u;
    TF_RND(13) TF_RND(15) TF_RND(26) TF_RND(6)   x0 += ks2; x1 += ks0 + 5u;
#undef TF_RND
    o0 = x0; o1 = x1;
}

// Partitionable mode (default since JAX 0.5): counter=(hi=0, lo=n), xor-fold.
__device__ __forceinline__ uint32_t jax_bits_part(uint32_t n) {
    uint32_t o0, o1;
    tf2x32(0u, n, o0, o1);
    return o0 ^ o1;
}

// Legacy mode: counts=iota split in halves; block j = (j, j+H).
__device__ __forceinline__ uint32_t jax_bits_legacy(uint32_t n, uint32_t H) {
    uint32_t o0, o1;
    uint32_t j = (n < H) ? n : (n - H);
    tf2x32(j, j + H, o0, o1);
    return (n < H) ? o0 : o1;
}

// gumbel = -log(-log(uniform(tiny, 1)));  u01 = bitcast((bits>>9)|1.0f) - 1
__device__ __forceinline__ float bits_to_gumbel(uint32_t bits) {
    const float TINY = 1.17549435e-38f;  // finfo(f32).tiny
    float u01 = __uint_as_float((bits >> 9) | 0x3f800000u) - 1.0f;
    float u = fmaxf(TINY, u01 + TINY);
    return -logf(-logf(u));
}

// Monotone float -> sortable uint32 map
__device__ __forceinline__ uint32_t f2s(float f) {
    uint32_t u = __float_as_uint(f);
    return u ^ (uint32_t)(((int32_t)u >> 31) | (int32_t)0x80000000);
}

// ---------------------------------------------------------------------------
// One CTA per row. Single HBM pass collects candidates (logit >= T); rare
// bisection retries re-read the row from L2. Then exact scaled values,
// k-th selection, gumbel perturbation, and first-index-tie-break argmax.
// OUTPUT IS WRITTEN AS FLOAT32 (harness output dtype).
// ---------------------------------------------------------------------------
__global__ __launch_bounds__(NTHREADS)
void sampler_kernel(const float* __restrict__ logits,
                    const float* __restrict__ temps,
                    int          k,
                    float*       __restrict__ out,
                    uint32_t     H)
{
    __shared__ float s_val[CAP];
    __shared__ int   s_idx[CAP];
    __shared__ int   s_cnt;
    __shared__ float s_kth;
    __shared__ unsigned long long s_best;
    __shared__ unsigned long long s_best_leg;   // row-0 diagnostics only

    const int row = blockIdx.x;
    const int tid = threadIdx.x;
    const float temp = temps[row];
    const float4* __restrict__ rowp =
        reinterpret_cast<const float4*>(logits + (size_t)row * VV);

    if (tid == 0) {
        s_cnt = 0; s_best = 0ull; s_best_leg = 0ull;
        s_kth = __int_as_float(0xFF800000);
    }
    __syncthreads();

    // Threshold bisection: first guess 3.0 works for N(0,1) rows with k=50.
    float Tlo = -3.0e38f, Thi = 3.0e38f;
    float T = 3.0f;
    int cnt = 0;

    for (int attempt = 0; attempt < 48; ++attempt) {
        #pragma unroll 4
        for (int i = tid; i < VV4; i += NTHREADS) {
            float4 v = rowp[i];
            float m = fmaxf(fmaxf(v.x, v.y), fmaxf(v.z, v.w));
            if (m >= T) {
                float xs[4] = {v.x, v.y, v.z, v.w};
                #pragma unroll
                for (int e = 0; e < 4; ++e) {
                    if (xs[e] >= T) {
                        int p = atomicAdd(&s_cnt, 1);
                        if (p < CAP) { s_val[p] = xs[e]; s_idx[p] = i * 4 + e; }
                    }
                }
            }
        }
        __syncthreads();
        cnt = s_cnt;
        if (cnt >= k && cnt <= CAP) break;
        if (cnt < k) { Thi = T; T = (Tlo < -1.0e38f) ? (T - 2.0f) : 0.5f * (Tlo + Thi); }
        else         { Tlo = T; T = (Thi >  1.0e38f) ? (T + 2.0f) : 0.5f * (Tlo + Thi); }
        __syncthreads();
        if (tid == 0) s_cnt = 0;
        __syncthreads();
    }
    cnt = min(cnt, CAP);

    // --- exact temperature scaling (bit-matches reference's f32 division) ---
    for (int i = tid; i < cnt; i += NTHREADS)
        s_val[i] = __fdiv_rn(s_val[i], temp);
    __syncthreads();

    // --- k-th largest among candidates (counting duplicates) ---
    for (int i = tid; i < cnt; i += NTHREADS) {
        float v = s_val[i];
        int cg = 0, ce = 0;
        for (int j = 0; j < cnt; ++j) {
            float u = s_val[j];
            cg += (u > v);
            ce += (u == v);
        }
        if (cg < k && cg + ce >= k) s_kth = v;  // unique value; benign race
    }
    __syncthreads();
    float kv = s_kth;

    // --- gumbel-perturbed argmax over {scaled >= kth}; first-index ties ---
    for (int i = tid; i < cnt; i += NTHREADS) {
        float v = s_val[i];
        if (v >= kv) {
            int col = s_idx[i];
            uint32_t n = (uint32_t)row * (uint32_t)VV + (uint32_t)col;
            float tot = v + bits_to_gumbel(jax_bits_part(n));
            unsigned long long pack =
                ((unsigned long long)f2s(tot) << 32) |
                (unsigned long long)(0xFFFFFFFFu - (uint32_t)col);
            atomicMax(&s_best, pack);
            if (row == 0) {  // diagnostic: legacy-mode pick for row 0
                float tl = v + bits_to_gumbel(jax_bits_legacy(n, H));
                unsigned long long pl =
                    ((unsigned long long)f2s(tl) << 32) |
                    (unsigned long long)(0xFFFFFFFFu - (uint32_t)col);
                atomicMax(&s_best_leg, pl);
            }
        }
    }
    __syncthreads();

    if (tid == 0) {
        int win = (int)(0xFFFFFFFFu - (uint32_t)(s_best & 0xFFFFFFFFull));
        out[row] = (float)win;   // FLOAT32 output
        if (row == 0) {
            int winl = (int)(0xFFFFFFFFu - (uint32_t)(s_best_leg & 0xFFFFFFFFull));
            printf("DIAG row0: cnt=%d kth=%.9g col_part=%d col_legacy=%d\n",
                   cnt, kv, win, winl);
        }
    }
}

extern "C" void kernel_launch(void* const* d_in, const int* in_sizes, int n_in,
                              void* d_out, int out_size)
{
    static int printed = 0;
    if (!printed) {
        printed = 1;
        printf("DIAG host: n_in=%d out_size=%d sizes:", n_in, out_size);
        for (int i = 0; i < n_in && i < 6; ++i) printf(" [%d]=%d", i, in_sizes[i]);
        printf("\n");
        fflush(stdout);
    }

    const float* logits = (const float*)d_in[0];
    const float* temps  = (const float*)d_in[1];
    float* out = (float*)d_out;

    int Brows = (n_in >= 2 && in_sizes[1] > 0) ? in_sizes[1] : 256;   // 256
    uint32_t H = (uint32_t)Brows * (uint32_t)VV / 2u;                 // legacy half
    sampler_kernel<<<Brows, NTHREADS>>>(logits, temps, /*k=*/50, out, H);
}

// round 5
// speedup vs baseline: 1.3511x; 1.3511x over previous
#include <cuda_runtime.h>
#include <stdint.h>

// Fixed problem shape
#define VV        128000
#define VV4       (VV / 4)
#define ROWS_MAX  256
#define CAP       2048
#define KTOP      50
#define THRESH    3.0f

// Scan decomposition: 16 chunks/row * 2000 float4 = 32000 float4 = VV4 exactly
#define SCAN_THREADS   256
#define CHUNK_F4       2000
#define CHUNKS_PER_ROW 16
#define UNROLL         8

// Global scratch (device globals: allowed; zero-initialized at module load,
// and select_kernel re-zeroes counters so every graph replay starts clean).
__device__ int   g_cnt[ROWS_MAX];
__device__ float g_vals[ROWS_MAX][CAP];
__device__ int   g_idx[ROWS_MAX][CAP];

// ---------------------------------------------------------------------------
// JAX threefry2x32, partitionable mode. key = jax.random.key(42) -> (0, 42).
// counter = (hi32(n)=0, lo32(n)=n); 32-bit output = lane0 ^ lane1.
// ---------------------------------------------------------------------------
__device__ __forceinline__ uint32_t rotl32(uint32_t x, int r) {
    return (x << r) | (x >> (32 - r));
}

__device__ __forceinline__ uint32_t jax_bits_part(uint32_t n) {
    const uint32_t ks0 = 0u;
    const uint32_t ks1 = 42u;
    const uint32_t ks2 = 0x1BD11BDAu ^ 0u ^ 42u;   // 0x1BD11BF0
    uint32_t x0 = 0u + ks0;
    uint32_t x1 = n  + ks1;
#define TF_RND(r) { x0 += x1; x1 = rotl32(x1, (r)); x1 ^= x0; }
    TF_RND(13) TF_RND(15) TF_RND(26) TF_RND(6)   x0 += ks1; x1 += ks2 + 1u;
    TF_RND(17) TF_RND(29) TF_RND(16) TF_RND(24)  x0 += ks2; x1 += ks0 + 2u;
    TF_RND(13) TF_RND(15) TF_RND(26) TF_RND(6)   x0 += ks0; x1 += ks1 + 3u;
    TF_RND(17) TF_RND(29) TF_RND(16) TF_RND(24)  x0 += ks1; x1 += ks2 + 4u;
    TF_RND(13) TF_RND(15) TF_RND(26) TF_RND(6)   x0 += ks2; x1 += ks0 + 5u;
#undef TF_RND
    return x0 ^ x1;
}

// gumbel = -log(-log(uniform(tiny, 1)))
__device__ __forceinline__ float jax_gumbel(uint32_t n) {
    const float TINY = 1.17549435e-38f;
    uint32_t bits = jax_bits_part(n);
    float u01 = __uint_as_float((bits >> 9) | 0x3f800000u) - 1.0f;
    float u = fmaxf(TINY, u01 + TINY);
    return -logf(-logf(u));
}

// Monotone float -> sortable uint32 map
__device__ __forceinline__ uint32_t f2s(float f) {
    uint32_t u = __float_as_uint(f);
    return u ^ (uint32_t)(((int32_t)u >> 31) | (int32_t)0x80000000);
}

// ---------------------------------------------------------------------------
// Kernel 1: flat HBM sweep. One CTA scans one 2000-float4 chunk of one row.
// 8 front-batched LDG.128 per thread for memory-level parallelism.
// Candidates (raw logit >= THRESH) appended to per-row global lists.
// ---------------------------------------------------------------------------
__global__ __launch_bounds__(SCAN_THREADS)
void scan_kernel(const float* __restrict__ logits)
{
    const int chunk = blockIdx.x;
    const int row   = chunk >> 4;          // /CHUNKS_PER_ROW
    const int seg   = chunk & 15;
    const int t     = threadIdx.x;
    const int base  = seg * CHUNK_F4;
    const float4* __restrict__ rowp =
        reinterpret_cast<const float4*>(logits + (size_t)row * VV);

    float4 v[UNROLL];
    #pragma unroll
    for (int j = 0; j < UNROLL; ++j) {
        int o = j * SCAN_THREADS + t;
        v[j] = (o < CHUNK_F4) ? __ldg(&rowp[base + o])
                              : make_float4(-1e30f, -1e30f, -1e30f, -1e30f);
    }

    #pragma unroll
    for (int j = 0; j < UNROLL; ++j) {
        float m = fmaxf(fmaxf(v[j].x, v[j].y), fmaxf(v[j].z, v[j].w));
        if (m >= THRESH) {   // rare (~0.5% of float4 groups)
            int o = j * SCAN_THREADS + t;
            float xs[4] = {v[j].x, v[j].y, v[j].z, v[j].w};
            #pragma unroll
            for (int e = 0; e < 4; ++e) {
                if (xs[e] >= THRESH) {
                    int p = atomicAdd(&g_cnt[row], 1);
                    if (p < CAP) {
                        g_vals[row][p] = xs[e];
                        g_idx[row][p]  = (base + o) * 4 + e;
                    }
                }
            }
        }
    }
}

// ---------------------------------------------------------------------------
// Kernel 2: per-row selection + sampling. One CTA (256 threads) per row.
// Normal path: candidates from global scratch. Fallback (never taken for
// this input, kept for correctness): bisection rescan of the full row.
// Resets g_cnt[row] for the next graph replay.
// ---------------------------------------------------------------------------
__global__ __launch_bounds__(256)
void select_kernel(const float* __restrict__ logits,
                   const float* __restrict__ temps,
                   float*       __restrict__ out)
{
    __shared__ float s_val[CAP];
    __shared__ int   s_idx[CAP];
    __shared__ int   s_cnt;
    __shared__ float s_kth;
    __shared__ unsigned long long s_best;

    const int row = blockIdx.x;
    const int tid = threadIdx.x;
    const int k   = KTOP;
    const float temp = temps[row];

    if (tid == 0) { s_best = 0ull; s_kth = __int_as_float(0xFF800000); }
    __syncthreads();

    int cnt = g_cnt[row];

    if (cnt >= k && cnt <= CAP) {
        for (int i = tid; i < cnt; i += 256) {
            s_val[i] = g_vals[row][i];
            s_idx[i] = g_idx[row][i];
        }
        __syncthreads();
    } else {
        // Fallback: bisection rescan of the row (L2-resident after scan pass).
        const float4* __restrict__ rowp =
            reinterpret_cast<const float4*>(logits + (size_t)row * VV);
        if (tid == 0) s_cnt = 0;
        __syncthreads();
        float Tlo = -3.0e38f, Thi = 3.0e38f, T = THRESH;
        int c = 0;
        for (int attempt = 0; attempt < 48; ++attempt) {
            for (int i = tid; i < VV4; i += 256) {
                float4 v = rowp[i];
                float m = fmaxf(fmaxf(v.x, v.y), fmaxf(v.z, v.w));
                if (m >= T) {
                    float xs[4] = {v.x, v.y, v.z, v.w};
                    #pragma unroll
                    for (int e = 0; e < 4; ++e) {
                        if (xs[e] >= T) {
                            int p = atomicAdd(&s_cnt, 1);
                            if (p < CAP) { s_val[p] = xs[e]; s_idx[p] = i * 4 + e; }
                        }
                    }
                }
            }
            __syncthreads();
            c = s_cnt;
            if (c >= k && c <= CAP) break;
            if (c < k) { Thi = T; T = (Tlo < -1.0e38f) ? (T - 2.0f) : 0.5f * (Tlo + Thi); }
            else       { Tlo = T; T = (Thi >  1.0e38f) ? (T + 2.0f) : 0.5f * (Tlo + Thi); }
            __syncthreads();
            if (tid == 0) s_cnt = 0;
            __syncthreads();
        }
        cnt = min(c, CAP);
    }

    // Exact temperature scaling (bit-matches reference's f32 division).
    for (int i = tid; i < cnt; i += 256)
        s_val[i] = __fdiv_rn(s_val[i], temp);
    __syncthreads();

    // k-th largest among candidates (duplicate-aware rank count).
    for (int i = tid; i < cnt; i += 256) {
        float v = s_val[i];
        int cg = 0, ce = 0;
        for (int j = 0; j < cnt; ++j) {
            float u = s_val[j];
            cg += (u > v);
            ce += (u == v);
        }
        if (cg < k && cg + ce >= k) s_kth = v;  // unique value; benign race
    }
    __syncthreads();
    float kv = s_kth;

    // Gumbel-perturbed argmax over {scaled >= kth}; first-index tie-break.
    for (int i = tid; i < cnt; i += 256) {
        float v = s_val[i];
        if (v >= kv) {
            int col = s_idx[i];
            uint32_t n = (uint32_t)row * (uint32_t)VV + (uint32_t)col;
            float tot = v + jax_gumbel(n);
            unsigned long long pack =
                ((unsigned long long)f2s(tot) << 32) |
                (unsigned long long)(0xFFFFFFFFu - (uint32_t)col);
            atomicMax(&s_best, pack);
        }
    }
    __syncthreads();

    if (tid == 0) {
        int win = (int)(0xFFFFFFFFu - (uint32_t)(s_best & 0xFFFFFFFFull));
        out[row] = (float)win;        // harness output dtype is float32
        g_cnt[row] = 0;               // re-arm for next graph replay
    }
}

extern "C" void kernel_launch(void* const* d_in, const int* in_sizes, int n_in,
                              void* d_out, int out_size)
{
    const float* logits = (const float*)d_in[0];
    const float* temps  = (const float*)d_in[1];
    float* out = (float*)d_out;

    int rows = (n_in >= 2 && in_sizes[1] > 0) ? in_sizes[1] : ROWS_MAX;  // 256

    scan_kernel<<<rows * CHUNKS_PER_ROW, SCAN_THREADS>>>(logits);
    select_kernel<<<rows, 256>>>(logits, temps, out);
}